// round 1
// baseline (speedup 1.0000x reference)
#include <cuda_runtime.h>
#include <cuda_bf16.h>
#include <math.h>

// Problem constants
#define B_  4
#define L_  2048
#define D_  1024
#define H_  16
#define DK_ 64
#define M_  (B_ * L_)      // 8192 rows of the projection GEMMs
#define N_  (H_ * DK_)     // 1024 cols

// Scratch (device globals — no runtime allocation allowed)
__device__ float g_q[B_ * H_ * L_ * DK_];    // [B,H,L,DK]
__device__ float g_k[B_ * H_ * L_ * DK_];
__device__ float g_v[B_ * H_ * L_ * DK_];
__device__ float g_ctx[B_ * L_ * H_ * DK_];  // [B,L,H*DV]

// ---------------------------------------------------------------------------
// Tiled GEMM: C[M=8192, N=1024] = A[8192,1024] @ W[1024,1024] + bias
// Block tile 64x64, K-tile 16, 256 threads, 4x4 per thread.
// SPLIT=true  -> store to [B,H,L,DK] layout (head split)
// SPLIT=false -> store row-major [M,N]
// ---------------------------------------------------------------------------
template <bool SPLIT>
__global__ __launch_bounds__(256) void gemm64(const float* __restrict__ A,
                                              const float* __restrict__ W,
                                              const float* __restrict__ bias,
                                              float* __restrict__ C) {
    __shared__ float As[16][64];  // [k][row]  (transposed: conflict-free reads)
    __shared__ float Ws[16][64];  // [k][col]

    const int tid = threadIdx.x;
    const int tx = tid & 15;
    const int ty = tid >> 4;
    const int row0 = blockIdx.y * 64;
    const int col0 = blockIdx.x * 64;

    // loader indices
    const int la_row = tid >> 2;        // 0..63
    const int la_k   = (tid & 3) * 4;   // 0,4,8,12
    const int lw_k   = tid >> 4;        // 0..15
    const int lw_c   = (tid & 15) * 4;  // 0..60

    float acc[4][4];
#pragma unroll
    for (int i = 0; i < 4; i++)
#pragma unroll
        for (int j = 0; j < 4; j++) acc[i][j] = 0.0f;

    for (int k0 = 0; k0 < D_; k0 += 16) {
        float4 av = *(const float4*)&A[(row0 + la_row) * D_ + k0 + la_k];
        As[la_k + 0][la_row] = av.x;
        As[la_k + 1][la_row] = av.y;
        As[la_k + 2][la_row] = av.z;
        As[la_k + 3][la_row] = av.w;
        *(float4*)&Ws[lw_k][lw_c] =
            *(const float4*)&W[(k0 + lw_k) * N_ + col0 + lw_c];
        __syncthreads();

#pragma unroll
        for (int k = 0; k < 16; k++) {
            float4 a4 = *(const float4*)&As[k][ty * 4];
            float4 b4 = *(const float4*)&Ws[k][tx * 4];
            float aa[4] = {a4.x, a4.y, a4.z, a4.w};
            float bb[4] = {b4.x, b4.y, b4.z, b4.w};
#pragma unroll
            for (int i = 0; i < 4; i++)
#pragma unroll
                for (int j = 0; j < 4; j++) acc[i][j] += aa[i] * bb[j];
        }
        __syncthreads();
    }

#pragma unroll
    for (int i = 0; i < 4; i++) {
        const int m = row0 + ty * 4 + i;
#pragma unroll
        for (int j = 0; j < 4; j++) {
            const int n = col0 + tx * 4 + j;
            const float v = acc[i][j] + bias[n];
            if (SPLIT) {
                const int b = m >> 11;       // / L_
                const int l = m & (L_ - 1);
                const int h = n >> 6;        // / DK_
                const int dk = n & (DK_ - 1);
                C[(((b * H_ + h) * L_) + l) * DK_ + dk] = v;
            } else {
                C[m * N_ + n] = v;
            }
        }
    }
}

// ---------------------------------------------------------------------------
// Flash attention: one (b,h) head slice, 64 query rows per block.
// q,k,v in [B,H,L,64] layout. Writes ctx in [B,L,H*64] layout.
// smem: Qt[k][row], KPt (K as [k][col], reused as P^T [p][row]), Vs[p][col]
// 3 * 16KB = 48KB static shared.
// ---------------------------------------------------------------------------
__global__ __launch_bounds__(256) void attn_kernel(const float* __restrict__ q,
                                                   const float* __restrict__ k,
                                                   const float* __restrict__ v,
                                                   float* __restrict__ ctx) {
    __shared__ float Qt[64][64];   // [k][row], pre-scaled by 1/sqrt(dk)
    __shared__ float KPt[64][64];  // phase 1: K^T [k][col]; phase 2: P^T [p][row]
    __shared__ float Vs[64][64];   // [p][col]

    const int tid = threadIdx.x;
    const int tx = tid & 15;
    const int ty = tid >> 4;
    const int bh = blockIdx.y;           // b*H + h
    const int q0 = blockIdx.x * 64;
    const float scale = 0.125f;          // 1/sqrt(64)

    const float* qbase = q + (size_t)bh * L_ * DK_ + (size_t)q0 * DK_;
    const float* kbase = k + (size_t)bh * L_ * DK_;
    const float* vbase = v + (size_t)bh * L_ * DK_;

    // Load Q tile (64x64), store transposed, pre-scaled
#pragma unroll
    for (int it = 0; it < 4; it++) {
        const int f = it * 256 + tid;      // float4 index 0..1023
        const int r = f >> 4;
        const int c4 = (f & 15) * 4;
        float4 av = *(const float4*)&qbase[r * DK_ + c4];
        Qt[c4 + 0][r] = av.x * scale;
        Qt[c4 + 1][r] = av.y * scale;
        Qt[c4 + 2][r] = av.z * scale;
        Qt[c4 + 3][r] = av.w * scale;
    }

    float m_i[4], l_i[4], o[4][4];
#pragma unroll
    for (int i = 0; i < 4; i++) {
        m_i[i] = -1e30f;
        l_i[i] = 0.0f;
#pragma unroll
        for (int j = 0; j < 4; j++) o[i][j] = 0.0f;
    }

    for (int j0 = 0; j0 < L_; j0 += 64) {
        __syncthreads();  // prior P reads done (also covers initial Q stores)

        // Load K tile transposed, V tile straight
#pragma unroll
        for (int it = 0; it < 4; it++) {
            const int f = it * 256 + tid;
            const int r = f >> 4;
            const int c4 = (f & 15) * 4;
            float4 kv = *(const float4*)&kbase[(j0 + r) * DK_ + c4];
            KPt[c4 + 0][r] = kv.x;
            KPt[c4 + 1][r] = kv.y;
            KPt[c4 + 2][r] = kv.z;
            KPt[c4 + 3][r] = kv.w;
            *(float4*)&Vs[r][c4] = *(const float4*)&vbase[(j0 + r) * DK_ + c4];
        }
        __syncthreads();

        // S = (Q/sqrt(dk)) K^T : s[i][j] over k
        float s[4][4];
#pragma unroll
        for (int i = 0; i < 4; i++)
#pragma unroll
            for (int j = 0; j < 4; j++) s[i][j] = 0.0f;

#pragma unroll
        for (int kk = 0; kk < 64; kk++) {
            float4 a4 = *(const float4*)&Qt[kk][ty * 4];
            float4 b4 = *(const float4*)&KPt[kk][tx * 4];
            float aa[4] = {a4.x, a4.y, a4.z, a4.w};
            float bb[4] = {b4.x, b4.y, b4.z, b4.w};
#pragma unroll
            for (int i = 0; i < 4; i++)
#pragma unroll
                for (int j = 0; j < 4; j++) s[i][j] += aa[i] * bb[j];
        }

        // Online softmax update (rows owned by same-ty 16-lane group)
        float p[4][4];
#pragma unroll
        for (int i = 0; i < 4; i++) {
            float mm = fmaxf(fmaxf(s[i][0], s[i][1]), fmaxf(s[i][2], s[i][3]));
#pragma unroll
            for (int d = 1; d < 16; d <<= 1)
                mm = fmaxf(mm, __shfl_xor_sync(0xffffffffu, mm, d));
            const float mnew = fmaxf(m_i[i], mm);
            const float alpha = __expf(m_i[i] - mnew);
            l_i[i] *= alpha;
#pragma unroll
            for (int j = 0; j < 4; j++) o[i][j] *= alpha;
            float sum = 0.0f;
#pragma unroll
            for (int j = 0; j < 4; j++) {
                p[i][j] = __expf(s[i][j] - mnew);
                sum += p[i][j];
            }
#pragma unroll
            for (int d = 1; d < 16; d <<= 1)
                sum += __shfl_xor_sync(0xffffffffu, sum, d);
            l_i[i] += sum;
            m_i[i] = mnew;
        }

        __syncthreads();  // everyone done reading K before overwrite with P^T
#pragma unroll
        for (int i = 0; i < 4; i++)
#pragma unroll
            for (int j = 0; j < 4; j++)
                KPt[tx * 4 + j][ty * 4 + i] = p[i][j];
        __syncthreads();

        // O += P V : o[i][j] over p
#pragma unroll
        for (int pp = 0; pp < 64; pp++) {
            float4 a4 = *(const float4*)&KPt[pp][ty * 4];
            float4 b4 = *(const float4*)&Vs[pp][tx * 4];
            float aa[4] = {a4.x, a4.y, a4.z, a4.w};
            float bb[4] = {b4.x, b4.y, b4.z, b4.w};
#pragma unroll
            for (int i = 0; i < 4; i++)
#pragma unroll
                for (int j = 0; j < 4; j++) o[i][j] += aa[i] * bb[j];
        }
    }

    // Write ctx [B, L, H*DV]
    const int b = bh >> 4;
    const int h = bh & (H_ - 1);
#pragma unroll
    for (int i = 0; i < 4; i++) {
        const int r = q0 + ty * 4 + i;
        const float inv_l = 1.0f / l_i[i];
#pragma unroll
        for (int j = 0; j < 4; j++) {
            ctx[((size_t)b * L_ + r) * (H_ * DK_) + h * DK_ + tx * 4 + j] =
                o[i][j] * inv_l;
        }
    }
}

// ---------------------------------------------------------------------------
extern "C" void kernel_launch(void* const* d_in, const int* in_sizes, int n_in,
                              void* d_out, int out_size) {
    const float* query = (const float*)d_in[0];
    const float* key   = (const float*)d_in[1];
    const float* value = (const float*)d_in[2];
    const float* W_q   = (const float*)d_in[3];
    const float* b_q   = (const float*)d_in[4];
    const float* W_k   = (const float*)d_in[5];
    const float* b_k   = (const float*)d_in[6];
    const float* W_v   = (const float*)d_in[7];
    const float* b_v   = (const float*)d_in[8];
    const float* W_o   = (const float*)d_in[9];
    const float* b_o   = (const float*)d_in[10];
    float* out = (float*)d_out;

    float *qp, *kp, *vp, *cp;
    cudaGetSymbolAddress((void**)&qp, g_q);
    cudaGetSymbolAddress((void**)&kp, g_k);
    cudaGetSymbolAddress((void**)&vp, g_v);
    cudaGetSymbolAddress((void**)&cp, g_ctx);

    dim3 ggrid(N_ / 64, M_ / 64);  // (16, 128)
    gemm64<true><<<ggrid, 256>>>(query, W_q, b_q, qp);
    gemm64<true><<<ggrid, 256>>>(key, W_k, b_k, kp);
    gemm64<true><<<ggrid, 256>>>(value, W_v, b_v, vp);

    dim3 agrid(L_ / 64, B_ * H_);  // (32, 64)
    attn_kernel<<<agrid, 256>>>(qp, kp, vp, cp);

    gemm64<false><<<ggrid, 256>>>(cp, W_o, b_o, out);
}

// round 2
// speedup vs baseline: 3.7996x; 3.7996x over previous
#include <cuda_runtime.h>
#include <cuda_bf16.h>
#include <math.h>
#include <stdint.h>

// Problem constants
#define B_  4
#define L_  2048
#define D_  1024
#define H_  16
#define DK_ 64
#define M_  (B_ * L_)      // 8192
#define N_  (H_ * DK_)     // 1024

// Scratch (device globals — no runtime allocation allowed)
__device__ float g_q[B_ * H_ * L_ * DK_];    // [B,H,L,DK]
__device__ float g_k[B_ * H_ * L_ * DK_];
__device__ float g_v[B_ * H_ * L_ * DK_];
__device__ float g_ctx[B_ * L_ * H_ * DK_];  // [B,L,H*DV]

// ---------------------------------------------------------------------------
// tf32 helpers
// ---------------------------------------------------------------------------
__device__ __forceinline__ uint32_t f2tf32(float v) {
    uint32_t r;
    asm("cvt.rna.tf32.f32 %0, %1;" : "=r"(r) : "f"(v));
    return r;
}

__device__ __forceinline__ void mma_tf32(float* c, const uint32_t* a,
                                         const uint32_t* b) {
    asm volatile(
        "mma.sync.aligned.m16n8k8.row.col.f32.tf32.tf32.f32 "
        "{%0,%1,%2,%3},{%4,%5,%6,%7},{%8,%9},{%0,%1,%2,%3};"
        : "+f"(c[0]), "+f"(c[1]), "+f"(c[2]), "+f"(c[3])
        : "r"(a[0]), "r"(a[1]), "r"(a[2]), "r"(a[3]), "r"(b[0]), "r"(b[1]));
}

// ---------------------------------------------------------------------------
// tf32 tensor-core GEMM: C[8192,1024] = A[8192,1024] @ W[1024,1024] + bias
// Block 128x128, BK=16, 256 threads (8 warps, 2x4), warp tile 64x32.
// Double-buffered smem; strides padded for conflict-free mma fragment LDS.
// ---------------------------------------------------------------------------
#define GA_STR 20    // 16 + 4 pad (words)
#define GB_STR 136   // 128 + 8 pad (words)

template <bool SPLIT>
__global__ __launch_bounds__(256, 2) void gemm_tf32(
    const float* __restrict__ A, const float* __restrict__ W,
    const float* __restrict__ bias, float* __restrict__ C) {
    __shared__ uint32_t As[2][128 * GA_STR];
    __shared__ uint32_t Bs[2][16 * GB_STR];

    const int tid = threadIdx.x;
    const int lane = tid & 31;
    const int warp = tid >> 5;
    const int wm = (warp >> 2) * 64;   // warp row offset
    const int wn = (warp & 3) * 32;    // warp col offset
    const int row0 = blockIdx.y * 128;
    const int col0 = blockIdx.x * 128;
    const int lr = lane >> 2;          // 0..7
    const int lc = lane & 3;           // 0..3

    float acc[4][4][4];
#pragma unroll
    for (int i = 0; i < 4; i++)
#pragma unroll
        for (int j = 0; j < 4; j++)
#pragma unroll
            for (int e = 0; e < 4; e++) acc[i][j][e] = 0.0f;

    // gmem load regs
    float4 ra[2], rb[2];

    // loader maps
    const int a_row[2] = {(0 * 256 + tid) >> 2, (1 * 256 + tid) >> 2};
    const int a_k = (tid & 3) * 4;
    const int b_row[2] = {(0 * 256 + tid) >> 5, (1 * 256 + tid) >> 5};
    const int b_c = (tid & 31) * 4;

    // prefetch tile 0
#pragma unroll
    for (int it = 0; it < 2; it++) {
        ra[it] = *(const float4*)&A[(size_t)(row0 + a_row[it]) * D_ + a_k];
        rb[it] = *(const float4*)&W[(size_t)b_row[it] * N_ + col0 + b_c];
    }

    int buf = 0;
    for (int kt = 0; kt < 64; kt++) {
        // STS (with tf32 convert)
#pragma unroll
        for (int it = 0; it < 2; it++) {
            uint32_t* pa = &As[buf][a_row[it] * GA_STR + a_k];
            pa[0] = f2tf32(ra[it].x); pa[1] = f2tf32(ra[it].y);
            pa[2] = f2tf32(ra[it].z); pa[3] = f2tf32(ra[it].w);
            uint32_t* pb = &Bs[buf][b_row[it] * GB_STR + b_c];
            pb[0] = f2tf32(rb[it].x); pb[1] = f2tf32(rb[it].y);
            pb[2] = f2tf32(rb[it].z); pb[3] = f2tf32(rb[it].w);
        }
        __syncthreads();

        if (kt < 63) {
            const int k0 = (kt + 1) * 16;
#pragma unroll
            for (int it = 0; it < 2; it++) {
                ra[it] = *(const float4*)&A[(size_t)(row0 + a_row[it]) * D_ + k0 + a_k];
                rb[it] = *(const float4*)&W[(size_t)(k0 + b_row[it]) * N_ + col0 + b_c];
            }
        }

        // compute from smem[buf]
#pragma unroll
        for (int ks = 0; ks < 2; ks++) {
            const int k = ks * 8;
            uint32_t af[4][4];
#pragma unroll
            for (int mt = 0; mt < 4; mt++) {
                const int r = wm + mt * 16 + lr;
                af[mt][0] = As[buf][r * GA_STR + k + lc];
                af[mt][1] = As[buf][(r + 8) * GA_STR + k + lc];
                af[mt][2] = As[buf][r * GA_STR + k + 4 + lc];
                af[mt][3] = As[buf][(r + 8) * GA_STR + k + 4 + lc];
            }
#pragma unroll
            for (int nt = 0; nt < 4; nt++) {
                uint32_t bf[2];
                const int c = wn + nt * 8 + lr;
                bf[0] = Bs[buf][(k + lc) * GB_STR + c];
                bf[1] = Bs[buf][(k + 4 + lc) * GB_STR + c];
#pragma unroll
                for (int mt = 0; mt < 4; mt++) mma_tf32(acc[mt][nt], af[mt], bf);
            }
        }
        buf ^= 1;
        __syncthreads();
    }

    // epilogue
#pragma unroll
    for (int mt = 0; mt < 4; mt++) {
#pragma unroll
        for (int nt = 0; nt < 4; nt++) {
            const int c = col0 + wn + nt * 8 + 2 * lc;
            const float bz0 = bias[c], bz1 = bias[c + 1];
#pragma unroll
            for (int half = 0; half < 2; half++) {
                const int m = row0 + wm + mt * 16 + lr + half * 8;
                const float v0 = acc[mt][nt][half * 2 + 0] + bz0;
                const float v1 = acc[mt][nt][half * 2 + 1] + bz1;
                if (SPLIT) {
                    const int b = m >> 11, l = m & (L_ - 1);
                    const int h = c >> 6, dk = c & (DK_ - 1);
                    float* p = &C[((((size_t)b * H_ + h) * L_) + l) * DK_ + dk];
                    p[0] = v0; p[1] = v1;
                } else {
                    C[(size_t)m * N_ + c] = v0;
                    C[(size_t)m * N_ + c + 1] = v1;
                }
            }
        }
    }
}

// ---------------------------------------------------------------------------
// Flash attention, tf32 tensor cores.
// Block: 128 query rows, iterate 64-key tiles. 8 warps, each owns 16 rows.
// smem (dynamic, 105472 B): Qt[128x68] Kt[64x68] Vt[64x72] Pt[128x68] (tf32)
// ---------------------------------------------------------------------------
#define QS_STR 68
#define KS_STR 68
#define VS_STR 72
#define PS_STR 68
#define ATTN_SMEM ((128 * QS_STR + 64 * KS_STR + 64 * VS_STR + 128 * PS_STR) * 4)

__global__ __launch_bounds__(256, 2) void attn_tf32(
    const float* __restrict__ q, const float* __restrict__ k,
    const float* __restrict__ v, float* __restrict__ ctx) {
    extern __shared__ uint32_t sm[];
    uint32_t* Qs = sm;
    uint32_t* Ks = Qs + 128 * QS_STR;
    uint32_t* Vs = Ks + 64 * KS_STR;
    uint32_t* Ps = Vs + 64 * VS_STR;

    const int tid = threadIdx.x;
    const int lane = tid & 31;
    const int warp = tid >> 5;
    const int lr = lane >> 2;
    const int lc = lane & 3;
    const int m0 = warp * 16;           // warp's query-row offset in tile
    const int bh = blockIdx.y;
    const int q0 = blockIdx.x * 128;

    const float* qbase = q + (size_t)bh * L_ * DK_ + (size_t)q0 * DK_;
    const float* kbase = k + (size_t)bh * L_ * DK_;
    const float* vbase = v + (size_t)bh * L_ * DK_;

    // Load Q tile (pre-scaled by 1/8, tf32)
#pragma unroll
    for (int it = 0; it < 8; it++) {
        const int fi = it * 256 + tid;
        const int r = fi >> 4, c4 = (fi & 15) * 4;
        float4 av = *(const float4*)&qbase[r * DK_ + c4];
        uint32_t* p = &Qs[r * QS_STR + c4];
        p[0] = f2tf32(av.x * 0.125f); p[1] = f2tf32(av.y * 0.125f);
        p[2] = f2tf32(av.z * 0.125f); p[3] = f2tf32(av.w * 0.125f);
    }

    float oacc[8][4];
#pragma unroll
    for (int vt = 0; vt < 8; vt++)
#pragma unroll
        for (int e = 0; e < 4; e++) oacc[vt][e] = 0.0f;
    float mrow0 = -1e30f, mrow1 = -1e30f, lrow0 = 0.0f, lrow1 = 0.0f;

    for (int j0 = 0; j0 < L_; j0 += 64) {
        __syncthreads();  // prior iteration's mma reads of Ks/Vs done

        // Load K, V tiles (tf32)
#pragma unroll
        for (int it = 0; it < 4; it++) {
            const int fi = it * 256 + tid;
            const int r = fi >> 4, c4 = (fi & 15) * 4;
            float4 kv = *(const float4*)&kbase[(size_t)(j0 + r) * DK_ + c4];
            uint32_t* pk = &Ks[r * KS_STR + c4];
            pk[0] = f2tf32(kv.x); pk[1] = f2tf32(kv.y);
            pk[2] = f2tf32(kv.z); pk[3] = f2tf32(kv.w);
            float4 vv = *(const float4*)&vbase[(size_t)(j0 + r) * DK_ + c4];
            uint32_t* pv = &Vs[r * VS_STR + c4];
            pv[0] = f2tf32(vv.x); pv[1] = f2tf32(vv.y);
            pv[2] = f2tf32(vv.z); pv[3] = f2tf32(vv.w);
        }
        __syncthreads();

        // S = Q Kt : 16 rows x 64 cols per warp
        float sacc[8][4];
#pragma unroll
        for (int nt = 0; nt < 8; nt++)
#pragma unroll
            for (int e = 0; e < 4; e++) sacc[nt][e] = 0.0f;

#pragma unroll
        for (int kt = 0; kt < 8; kt++) {
            const int kk = kt * 8;
            uint32_t af[4];
            af[0] = Qs[(m0 + lr) * QS_STR + kk + lc];
            af[1] = Qs[(m0 + lr + 8) * QS_STR + kk + lc];
            af[2] = Qs[(m0 + lr) * QS_STR + kk + 4 + lc];
            af[3] = Qs[(m0 + lr + 8) * QS_STR + kk + 4 + lc];
#pragma unroll
            for (int nt = 0; nt < 8; nt++) {
                uint32_t bf[2];
                bf[0] = Ks[(nt * 8 + lr) * KS_STR + kk + lc];
                bf[1] = Ks[(nt * 8 + lr) * KS_STR + kk + 4 + lc];
                mma_tf32(sacc[nt], af, bf);
            }
        }

        // Online softmax (rows lr and lr+8; stats shared across quad lanes)
        float mx0 = -1e30f, mx1 = -1e30f;
#pragma unroll
        for (int nt = 0; nt < 8; nt++) {
            mx0 = fmaxf(mx0, fmaxf(sacc[nt][0], sacc[nt][1]));
            mx1 = fmaxf(mx1, fmaxf(sacc[nt][2], sacc[nt][3]));
        }
        mx0 = fmaxf(mx0, __shfl_xor_sync(0xffffffffu, mx0, 1));
        mx0 = fmaxf(mx0, __shfl_xor_sync(0xffffffffu, mx0, 2));
        mx1 = fmaxf(mx1, __shfl_xor_sync(0xffffffffu, mx1, 1));
        mx1 = fmaxf(mx1, __shfl_xor_sync(0xffffffffu, mx1, 2));
        const float mn0 = fmaxf(mrow0, mx0);
        const float mn1 = fmaxf(mrow1, mx1);
        const float al0 = __expf(mrow0 - mn0);
        const float al1 = __expf(mrow1 - mn1);
        mrow0 = mn0; mrow1 = mn1;

        float sum0 = 0.0f, sum1 = 0.0f;
#pragma unroll
        for (int nt = 0; nt < 8; nt++) {
            float p0 = __expf(sacc[nt][0] - mn0);
            float p1 = __expf(sacc[nt][1] - mn0);
            float p2 = __expf(sacc[nt][2] - mn1);
            float p3 = __expf(sacc[nt][3] - mn1);
            sum0 += p0 + p1; sum1 += p2 + p3;
            const int c = nt * 8 + 2 * lc;
            uint32_t* pl = &Ps[(m0 + lr) * PS_STR + c];
            pl[0] = f2tf32(p0); pl[1] = f2tf32(p1);
            uint32_t* ph = &Ps[(m0 + lr + 8) * PS_STR + c];
            ph[0] = f2tf32(p2); ph[1] = f2tf32(p3);
        }
        sum0 += __shfl_xor_sync(0xffffffffu, sum0, 1);
        sum0 += __shfl_xor_sync(0xffffffffu, sum0, 2);
        sum1 += __shfl_xor_sync(0xffffffffu, sum1, 1);
        sum1 += __shfl_xor_sync(0xffffffffu, sum1, 2);
        lrow0 = lrow0 * al0 + sum0;
        lrow1 = lrow1 * al1 + sum1;
#pragma unroll
        for (int vt = 0; vt < 8; vt++) {
            oacc[vt][0] *= al0; oacc[vt][1] *= al0;
            oacc[vt][2] *= al1; oacc[vt][3] *= al1;
        }
        __syncwarp();  // P visible within warp (warp reads only its own rows)

        // O += P V
#pragma unroll
        for (int pt = 0; pt < 8; pt++) {
            const int pp = pt * 8;
            uint32_t af[4];
            af[0] = Ps[(m0 + lr) * PS_STR + pp + lc];
            af[1] = Ps[(m0 + lr + 8) * PS_STR + pp + lc];
            af[2] = Ps[(m0 + lr) * PS_STR + pp + 4 + lc];
            af[3] = Ps[(m0 + lr + 8) * PS_STR + pp + 4 + lc];
#pragma unroll
            for (int vt = 0; vt < 8; vt++) {
                uint32_t bf[2];
                bf[0] = Vs[(pp + lc) * VS_STR + vt * 8 + lr];
                bf[1] = Vs[(pp + 4 + lc) * VS_STR + vt * 8 + lr];
                mma_tf32(oacc[vt], af, bf);
            }
        }
    }

    // Epilogue: normalize and write ctx [B, L, H*DV]
    const int b = bh >> 4;
    const int h = bh & (H_ - 1);
    const float inv0 = 1.0f / lrow0;
    const float inv1 = 1.0f / lrow1;
    const int r0 = q0 + m0 + lr;
#pragma unroll
    for (int vt = 0; vt < 8; vt++) {
        const int c = h * DK_ + vt * 8 + 2 * lc;
        float* p0 = &ctx[((size_t)b * L_ + r0) * N_ + c];
        p0[0] = oacc[vt][0] * inv0; p0[1] = oacc[vt][1] * inv0;
        float* p1 = &ctx[((size_t)b * L_ + r0 + 8) * N_ + c];
        p1[0] = oacc[vt][2] * inv1; p1[1] = oacc[vt][3] * inv1;
    }
}

// ---------------------------------------------------------------------------
extern "C" void kernel_launch(void* const* d_in, const int* in_sizes, int n_in,
                              void* d_out, int out_size) {
    const float* query = (const float*)d_in[0];
    const float* key   = (const float*)d_in[1];
    const float* value = (const float*)d_in[2];
    const float* W_q   = (const float*)d_in[3];
    const float* b_q   = (const float*)d_in[4];
    const float* W_k   = (const float*)d_in[5];
    const float* b_k   = (const float*)d_in[6];
    const float* W_v   = (const float*)d_in[7];
    const float* b_v   = (const float*)d_in[8];
    const float* W_o   = (const float*)d_in[9];
    const float* b_o   = (const float*)d_in[10];
    float* out = (float*)d_out;

    float *qp, *kp, *vp, *cp;
    cudaGetSymbolAddress((void**)&qp, g_q);
    cudaGetSymbolAddress((void**)&kp, g_k);
    cudaGetSymbolAddress((void**)&vp, g_v);
    cudaGetSymbolAddress((void**)&cp, g_ctx);

    cudaFuncSetAttribute(attn_tf32, cudaFuncAttributeMaxDynamicSharedMemorySize,
                         ATTN_SMEM);

    dim3 ggrid(N_ / 128, M_ / 128);  // (8, 64)
    gemm_tf32<true><<<ggrid, 256>>>(query, W_q, b_q, qp);
    gemm_tf32<true><<<ggrid, 256>>>(key, W_k, b_k, kp);
    gemm_tf32<true><<<ggrid, 256>>>(value, W_v, b_v, vp);

    dim3 agrid(L_ / 128, B_ * H_);   // (16, 64)
    attn_tf32<<<agrid, 256, ATTN_SMEM>>>(qp, kp, vp, cp);

    gemm_tf32<false><<<ggrid, 256>>>(cp, W_o, b_o, out);
}

// round 4
// speedup vs baseline: 4.5829x; 1.2061x over previous
#include <cuda_runtime.h>
#include <cuda_bf16.h>
#include <math.h>
#include <stdint.h>

// Problem constants
#define B_  4
#define L_  2048
#define D_  1024
#define H_  16
#define DK_ 64
#define M_  (B_ * L_)      // 8192
#define N_  (H_ * DK_)     // 1024

// Scratch (device globals — no runtime allocation allowed)
__device__ float g_q[B_ * H_ * L_ * DK_];    // [B,H,L,DK] (tf32-rounded floats)
__device__ float g_k[B_ * H_ * L_ * DK_];
__device__ float g_v[B_ * H_ * L_ * DK_];
__device__ float g_ctx[B_ * L_ * H_ * DK_];  // [B,L,H*DV]
__device__ uint32_t g_wt[4ull * D_ * N_];    // tf32-rounded weights, [k][n]

// ---------------------------------------------------------------------------
// helpers
// ---------------------------------------------------------------------------
__device__ __forceinline__ uint32_t smem_u32(const void* p) {
    uint32_t a;
    asm("{ .reg .u64 t; cvta.to.shared.u64 t, %1; cvt.u32.u64 %0, t; }"
        : "=r"(a) : "l"(p));
    return a;
}
__device__ __forceinline__ uint32_t f2tf32(float v) {
    uint32_t r;
    asm("cvt.rna.tf32.f32 %0, %1;" : "=r"(r) : "f"(v));
    return r;
}
__device__ __forceinline__ void mma_tf32(float* c, const uint32_t* a,
                                         const uint32_t* b) {
    asm volatile(
        "mma.sync.aligned.m16n8k8.row.col.f32.tf32.tf32.f32 "
        "{%0,%1,%2,%3},{%4,%5,%6,%7},{%8,%9},{%0,%1,%2,%3};"
        : "+f"(c[0]), "+f"(c[1]), "+f"(c[2]), "+f"(c[3])
        : "r"(a[0]), "r"(a[1]), "r"(a[2]), "r"(a[3]), "r"(b[0]), "r"(b[1]));
}
#define CP_ASYNC16(dst, src)                                        \
    asm volatile("cp.async.cg.shared.global [%0], [%1], 16;" ::    \
                     "r"(dst), "l"(src))
#define CP_COMMIT() asm volatile("cp.async.commit_group;")
#define CP_WAIT0() asm volatile("cp.async.wait_group 0;")
#define CP_WAIT1() asm volatile("cp.async.wait_group 1;")

// ---------------------------------------------------------------------------
// Weight prepass: elementwise tf32 round (no transpose; B is consumed [k][n])
// ---------------------------------------------------------------------------
__global__ __launch_bounds__(256) void cvt_w(const float* __restrict__ W,
                                             uint32_t* __restrict__ Wt) {
    const int i = blockIdx.x * 1024 + threadIdx.x * 4;
    float4 v = *(const float4*)&W[i];
    uint4 o;
    o.x = f2tf32(v.x); o.y = f2tf32(v.y);
    o.z = f2tf32(v.z); o.w = f2tf32(v.w);
    *(uint4*)&Wt[i] = o;
}

// ---------------------------------------------------------------------------
// tf32 register-MMA GEMM with cp.async pipeline.
// C[8192,1024] = A @ W + bias. Tile 128x128, BK=32, 2 stages, 256 threads.
// A: LDG->cvt.rna->STS (register staged). B: cp.async (pre-rounded tf32).
// SPLIT=true: store to [B,H,L,DK] with tf32 rounding (consumed by attention).
// ---------------------------------------------------------------------------
#define AST 36    // A row stride words (32 + 4 pad)
#define BST 136   // B row stride words (128 + 8 pad)
#define ASW (128 * AST)                 // 4608 words
#define STGW (ASW + 32 * BST)           // 8960 words/stage
#define GEMM_SMEM (2 * STGW * 4)        // 71680 B

template <bool SPLIT>
__global__ __launch_bounds__(256, 2) void gemm_reg(
    const float* __restrict__ A, const uint32_t* __restrict__ Wt,
    const float* __restrict__ bias, float* __restrict__ C) {
    extern __shared__ uint32_t sh[];
    const uint32_t sbase = smem_u32(sh);
    const int tid = threadIdx.x;
    const int lane = tid & 31;
    const int warp = tid >> 5;
    const int wm = (warp >> 2) * 64;
    const int wn = (warp & 3) * 32;
    const int row0 = blockIdx.y * 128;
    const int col0 = blockIdx.x * 128;
    const int lr = lane >> 2;
    const int lc = lane & 3;

    float acc[4][4][4];
#pragma unroll
    for (int i = 0; i < 4; i++)
#pragma unroll
        for (int j = 0; j < 4; j++)
#pragma unroll
            for (int e = 0; e < 4; e++) acc[i][j][e] = 0.0f;

    float4 ar[4];

    auto ldgA = [&](int kt) {
#pragma unroll
        for (int it = 0; it < 4; it++) {
            const int cid = it * 256 + tid;
            ar[it] = *(const float4*)&A[(size_t)(row0 + (cid >> 3)) * D_ +
                                        kt * 32 + (cid & 7) * 4];
        }
    };
    auto stsA = [&](int s) {
#pragma unroll
        for (int it = 0; it < 4; it++) {
            const int cid = it * 256 + tid;
            uint32_t* p = &sh[s * STGW + (cid >> 3) * AST + (cid & 7) * 4];
            p[0] = f2tf32(ar[it].x); p[1] = f2tf32(ar[it].y);
            p[2] = f2tf32(ar[it].z); p[3] = f2tf32(ar[it].w);
        }
    };
    auto cpB = [&](int kt, int s) {
#pragma unroll
        for (int it = 0; it < 4; it++) {
            const int cid = it * 256 + tid;
            const uint32_t dst =
                sbase + (s * STGW + ASW + (cid >> 5) * BST + (cid & 31) * 4) * 4;
            const uint32_t* src =
                &Wt[(size_t)(kt * 32 + (cid >> 5)) * N_ + col0 + (cid & 31) * 4];
            CP_ASYNC16(dst, src);
        }
        CP_COMMIT();
    };

    // prologue
    ldgA(0);
    cpB(0, 0);

    for (int kt = 0; kt < 32; kt++) {
        const int s = kt & 1;
        stsA(s);
        if (kt < 31) {
            cpB(kt + 1, s ^ 1);
            CP_WAIT1();
        } else {
            CP_WAIT0();
        }
        __syncthreads();
        if (kt < 31) ldgA(kt + 1);

        const uint32_t* Ab = &sh[s * STGW];
        const uint32_t* Bb = &sh[s * STGW + ASW];
#pragma unroll
        for (int ks = 0; ks < 4; ks++) {
            const int k = ks * 8;
            uint32_t af[4][4];
#pragma unroll
            for (int mt = 0; mt < 4; mt++) {
                const int r = wm + mt * 16 + lr;
                af[mt][0] = Ab[r * AST + k + lc];
                af[mt][1] = Ab[(r + 8) * AST + k + lc];
                af[mt][2] = Ab[r * AST + k + 4 + lc];
                af[mt][3] = Ab[(r + 8) * AST + k + 4 + lc];
            }
#pragma unroll
            for (int nt = 0; nt < 4; nt++) {
                uint32_t bf[2];
                const int c = wn + nt * 8 + lr;
                bf[0] = Bb[(k + lc) * BST + c];
                bf[1] = Bb[(k + 4 + lc) * BST + c];
#pragma unroll
                for (int mt = 0; mt < 4; mt++) mma_tf32(acc[mt][nt], af[mt], bf);
            }
        }
        __syncthreads();
    }

    // epilogue
#pragma unroll
    for (int mt = 0; mt < 4; mt++) {
#pragma unroll
        for (int nt = 0; nt < 4; nt++) {
            const int c = col0 + wn + nt * 8 + 2 * lc;
            const float bz0 = bias[c], bz1 = bias[c + 1];
#pragma unroll
            for (int half = 0; half < 2; half++) {
                const int m = row0 + wm + mt * 16 + lr + half * 8;
                float v0 = acc[mt][nt][half * 2 + 0] + bz0;
                float v1 = acc[mt][nt][half * 2 + 1] + bz1;
                if (SPLIT) {
                    // round to tf32 so attention consumes raw bits
                    v0 = __uint_as_float(f2tf32(v0));
                    v1 = __uint_as_float(f2tf32(v1));
                    const int b = m >> 11, l = m & (L_ - 1);
                    const int h = c >> 6, dk = c & (DK_ - 1);
                    float* p = &C[((((size_t)b * H_ + h) * L_) + l) * DK_ + dk];
                    p[0] = v0; p[1] = v1;
                } else {
                    C[(size_t)m * N_ + c] = v0;
                    C[(size_t)m * N_ + c + 1] = v1;
                }
            }
        }
    }
}

// ---------------------------------------------------------------------------
// Flash attention, tf32 register MMA, cp.async double-buffered K/V,
// Q fragments in registers, P staged through smem (own-warp rows only).
// smem words: K[2][64*68] | V[2][64*72] | P[128*68]   (= 106496 B)
// ---------------------------------------------------------------------------
#define KSTR 68
#define VSTR 72
#define PSTR 68
#define KOFF(s) ((s) * (64 * KSTR))
#define VOFF(s) (2 * 64 * KSTR + (s) * (64 * VSTR))
#define POFF (2 * 64 * KSTR + 2 * 64 * VSTR)   // 17920
#define ATTN_SMEM ((POFF + 128 * PSTR) * 4)    // 106496

__global__ __launch_bounds__(256, 2) void attn2(
    const float* __restrict__ q, const float* __restrict__ k,
    const float* __restrict__ v, float* __restrict__ ctx) {
    extern __shared__ uint32_t sh[];
    const uint32_t sbase = smem_u32(sh);
    const int tid = threadIdx.x;
    const int lane = tid & 31;
    const int warp = tid >> 5;
    const int lr = lane >> 2;
    const int lc = lane & 3;
    const int m0 = warp * 16;
    const int bh = blockIdx.y;
    const int q0 = blockIdx.x * 128;

    const float* qbase = q + (size_t)bh * L_ * DK_ + (size_t)q0 * DK_;
    const float* kbase = k + (size_t)bh * L_ * DK_;
    const float* vbase = v + (size_t)bh * L_ * DK_;

    auto cpKV = [&](int jn, int s) {
#pragma unroll
        for (int it = 0; it < 4; it++) {
            const int cid = it * 256 + tid;
            const int row = cid >> 4;
            const int c4 = (cid & 15) * 4;
            const uint32_t dk = sbase + (KOFF(s) + row * KSTR + c4) * 4;
            CP_ASYNC16(dk, &kbase[(size_t)(jn * 64 + row) * DK_ + c4]);
            const uint32_t dv = sbase + (VOFF(s) + row * VSTR + c4) * 4;
            CP_ASYNC16(dv, &vbase[(size_t)(jn * 64 + row) * DK_ + c4]);
        }
        CP_COMMIT();
    };

    // stage Q into P region + first KV tile
#pragma unroll
    for (int it = 0; it < 8; it++) {
        const int cid = it * 256 + tid;
        const int row = cid >> 4;
        const int c4 = (cid & 15) * 4;
        const uint32_t dst = sbase + (POFF + row * PSTR + c4) * 4;
        CP_ASYNC16(dst, &qbase[(size_t)row * DK_ + c4]);
    }
    CP_COMMIT();
    cpKV(0, 0);
    CP_WAIT0();   // both groups (Q needed now; KV0 arrives with it)
    __syncthreads();

    // Q fragments -> registers (scaled by 1/sqrt(dk)=0.125, exact on tf32)
    uint32_t qf[8][4];
#pragma unroll
    for (int kt = 0; kt < 8; kt++) {
        const int kk = kt * 8;
        const uint32_t* P = &sh[POFF];
        uint32_t t0 = P[(m0 + lr) * PSTR + kk + lc];
        uint32_t t1 = P[(m0 + lr + 8) * PSTR + kk + lc];
        uint32_t t2 = P[(m0 + lr) * PSTR + kk + 4 + lc];
        uint32_t t3 = P[(m0 + lr + 8) * PSTR + kk + 4 + lc];
        qf[kt][0] = __float_as_uint(__uint_as_float(t0) * 0.125f);
        qf[kt][1] = __float_as_uint(__uint_as_float(t1) * 0.125f);
        qf[kt][2] = __float_as_uint(__uint_as_float(t2) * 0.125f);
        qf[kt][3] = __float_as_uint(__uint_as_float(t3) * 0.125f);
    }

    float oacc[8][4];
#pragma unroll
    for (int vt = 0; vt < 8; vt++)
#pragma unroll
        for (int e = 0; e < 4; e++) oacc[vt][e] = 0.0f;
    float mrow0 = -1e30f, mrow1 = -1e30f, lrow0 = 0.0f, lrow1 = 0.0f;

    for (int jt = 0; jt < 32; jt++) {
        const int s = jt & 1;
        if (jt > 0) {
            CP_WAIT0();        // KV(jt) arrived
            __syncthreads();   // and everyone finished jt-1
        }
        if (jt < 31) cpKV(jt + 1, s ^ 1);  // overlap with compute

        const uint32_t* Kb = &sh[KOFF(s)];
        const uint32_t* Vb = &sh[VOFF(s)];
        uint32_t* Pb = &sh[POFF];

        // S = Q K^T
        float sacc[8][4];
#pragma unroll
        for (int nt = 0; nt < 8; nt++)
#pragma unroll
            for (int e = 0; e < 4; e++) sacc[nt][e] = 0.0f;
#pragma unroll
        for (int kt = 0; kt < 8; kt++) {
            const int kk = kt * 8;
#pragma unroll
            for (int nt = 0; nt < 8; nt++) {
                uint32_t bf[2];
                bf[0] = Kb[(nt * 8 + lr) * KSTR + kk + lc];
                bf[1] = Kb[(nt * 8 + lr) * KSTR + kk + 4 + lc];
                mma_tf32(sacc[nt], qf[kt], bf);
            }
        }

        // online softmax
        float mx0 = -1e30f, mx1 = -1e30f;
#pragma unroll
        for (int nt = 0; nt < 8; nt++) {
            mx0 = fmaxf(mx0, fmaxf(sacc[nt][0], sacc[nt][1]));
            mx1 = fmaxf(mx1, fmaxf(sacc[nt][2], sacc[nt][3]));
        }
        mx0 = fmaxf(mx0, __shfl_xor_sync(0xffffffffu, mx0, 1));
        mx0 = fmaxf(mx0, __shfl_xor_sync(0xffffffffu, mx0, 2));
        mx1 = fmaxf(mx1, __shfl_xor_sync(0xffffffffu, mx1, 1));
        mx1 = fmaxf(mx1, __shfl_xor_sync(0xffffffffu, mx1, 2));
        const float mn0 = fmaxf(mrow0, mx0);
        const float mn1 = fmaxf(mrow1, mx1);
        const float al0 = __expf(mrow0 - mn0);
        const float al1 = __expf(mrow1 - mn1);
        mrow0 = mn0; mrow1 = mn1;

        float sum0 = 0.0f, sum1 = 0.0f;
#pragma unroll
        for (int nt = 0; nt < 8; nt++) {
            const float p0 = __expf(sacc[nt][0] - mn0);
            const float p1 = __expf(sacc[nt][1] - mn0);
            const float p2 = __expf(sacc[nt][2] - mn1);
            const float p3 = __expf(sacc[nt][3] - mn1);
            sum0 += p0 + p1; sum1 += p2 + p3;
            const int c = nt * 8 + 2 * lc;
            uint32_t* pl = &Pb[(m0 + lr) * PSTR + c];
            pl[0] = f2tf32(p0); pl[1] = f2tf32(p1);
            uint32_t* ph = &Pb[(m0 + lr + 8) * PSTR + c];
            ph[0] = f2tf32(p2); ph[1] = f2tf32(p3);
        }
        sum0 += __shfl_xor_sync(0xffffffffu, sum0, 1);
        sum0 += __shfl_xor_sync(0xffffffffu, sum0, 2);
        sum1 += __shfl_xor_sync(0xffffffffu, sum1, 1);
        sum1 += __shfl_xor_sync(0xffffffffu, sum1, 2);
        lrow0 = lrow0 * al0 + sum0;
        lrow1 = lrow1 * al1 + sum1;
#pragma unroll
        for (int vt = 0; vt < 8; vt++) {
            oacc[vt][0] *= al0; oacc[vt][1] *= al0;
            oacc[vt][2] *= al1; oacc[vt][3] *= al1;
        }
        __syncwarp();  // warp reads only its own P rows

        // O += P V
#pragma unroll
        for (int pt = 0; pt < 8; pt++) {
            const int pp = pt * 8;
            uint32_t af[4];
            af[0] = Pb[(m0 + lr) * PSTR + pp + lc];
            af[1] = Pb[(m0 + lr + 8) * PSTR + pp + lc];
            af[2] = Pb[(m0 + lr) * PSTR + pp + 4 + lc];
            af[3] = Pb[(m0 + lr + 8) * PSTR + pp + 4 + lc];
#pragma unroll
            for (int vt = 0; vt < 8; vt++) {
                uint32_t bf[2];
                bf[0] = Vb[(pp + lc) * VSTR + vt * 8 + lr];
                bf[1] = Vb[(pp + 4 + lc) * VSTR + vt * 8 + lr];
                mma_tf32(oacc[vt], af, bf);
            }
        }
        __syncthreads();  // all warps done with Ks[s]/Vs[s] before next overwrite
    }

    // epilogue: normalize, write ctx [B, L, H*DV]
    const int b = bh >> 4;
    const int h = bh & (H_ - 1);
    const float inv0 = 1.0f / lrow0;
    const float inv1 = 1.0f / lrow1;
    const int r0 = q0 + m0 + lr;
#pragma unroll
    for (int vt = 0; vt < 8; vt++) {
        const int c = h * DK_ + vt * 8 + 2 * lc;
        float* p0 = &ctx[((size_t)b * L_ + r0) * N_ + c];
        p0[0] = oacc[vt][0] * inv0; p0[1] = oacc[vt][1] * inv0;
        float* p1 = &ctx[((size_t)b * L_ + r0 + 8) * N_ + c];
        p1[0] = oacc[vt][2] * inv1; p1[1] = oacc[vt][3] * inv1;
    }
}

// ---------------------------------------------------------------------------
extern "C" void kernel_launch(void* const* d_in, const int* in_sizes, int n_in,
                              void* d_out, int out_size) {
    const float* query = (const float*)d_in[0];
    const float* key   = (const float*)d_in[1];
    const float* value = (const float*)d_in[2];
    const float* W_q   = (const float*)d_in[3];
    const float* b_q   = (const float*)d_in[4];
    const float* W_k   = (const float*)d_in[5];
    const float* b_k   = (const float*)d_in[6];
    const float* W_v   = (const float*)d_in[7];
    const float* b_v   = (const float*)d_in[8];
    const float* W_o   = (const float*)d_in[9];
    const float* b_o   = (const float*)d_in[10];
    float* out = (float*)d_out;

    float *qp, *kp, *vp, *cp;
    uint32_t* wt;
    cudaGetSymbolAddress((void**)&qp, g_q);
    cudaGetSymbolAddress((void**)&kp, g_k);
    cudaGetSymbolAddress((void**)&vp, g_v);
    cudaGetSymbolAddress((void**)&cp, g_ctx);
    cudaGetSymbolAddress((void**)&wt, g_wt);

    cudaFuncSetAttribute(gemm_reg<true>,
                         cudaFuncAttributeMaxDynamicSharedMemorySize, GEMM_SMEM);
    cudaFuncSetAttribute(gemm_reg<false>,
                         cudaFuncAttributeMaxDynamicSharedMemorySize, GEMM_SMEM);
    cudaFuncSetAttribute(attn2, cudaFuncAttributeMaxDynamicSharedMemorySize,
                         ATTN_SMEM);

    // weight prepass: tf32 rounding (1M elems each; 256 thr x 4 elems -> 1024 blocks)
    cvt_w<<<1024, 256>>>(W_q, wt + 0ull * D_ * N_);
    cvt_w<<<1024, 256>>>(W_k, wt + 1ull * D_ * N_);
    cvt_w<<<1024, 256>>>(W_v, wt + 2ull * D_ * N_);
    cvt_w<<<1024, 256>>>(W_o, wt + 3ull * D_ * N_);

    dim3 ggrid(N_ / 128, M_ / 128);  // (8, 64)
    gemm_reg<true><<<ggrid, 256, GEMM_SMEM>>>(query, wt + 0ull * D_ * N_, b_q, qp);
    gemm_reg<true><<<ggrid, 256, GEMM_SMEM>>>(key, wt + 1ull * D_ * N_, b_k, kp);
    gemm_reg<true><<<ggrid, 256, GEMM_SMEM>>>(value, wt + 2ull * D_ * N_, b_v, vp);

    dim3 agrid(L_ / 128, B_ * H_);   // (16, 64)
    attn2<<<agrid, 256, ATTN_SMEM>>>(qp, kp, vp, cp);

    gemm_reg<false><<<ggrid, 256, GEMM_SMEM>>>(cp, wt + 3ull * D_ * N_, b_o, out);
}

// round 8
// speedup vs baseline: 4.7569x; 1.0380x over previous
#include <cuda_runtime.h>
#include <cuda_bf16.h>
#include <math.h>
#include <stdint.h>

// Problem constants
#define B_  4
#define L_  2048
#define D_  1024
#define H_  16
#define DK_ 64
#define M_  (B_ * L_)      // 8192
#define N_  (H_ * DK_)     // 1024

// Scratch (device globals — no runtime allocation allowed)
__device__ float g_q[B_ * H_ * L_ * DK_];    // [B,H,L,DK] (tf32-rounded floats)
__device__ float g_k[B_ * H_ * L_ * DK_];
__device__ float g_v[B_ * H_ * L_ * DK_];
__device__ float g_ctx[B_ * L_ * H_ * DK_];  // [B,L,H*DV]
__device__ uint32_t g_wt[4ull * D_ * N_];    // tf32-rounded weights, [k][n]

// ---------------------------------------------------------------------------
// helpers
// ---------------------------------------------------------------------------
__device__ __forceinline__ uint32_t smem_u32(const void* p) {
    uint32_t a;
    asm("{ .reg .u64 t; cvta.to.shared.u64 t, %1; cvt.u32.u64 %0, t; }"
        : "=r"(a) : "l"(p));
    return a;
}
__device__ __forceinline__ uint32_t f2tf32(float v) {
    uint32_t r;
    asm("cvt.rna.tf32.f32 %0, %1;" : "=r"(r) : "f"(v));
    return r;
}
__device__ __forceinline__ float ex2(float x) {
    float r;
    asm("ex2.approx.ftz.f32 %0, %1;" : "=f"(r) : "f"(x));
    return r;
}
__device__ __forceinline__ void mma_tf32(float* c, const uint32_t* a,
                                         const uint32_t* b) {
    asm volatile(
        "mma.sync.aligned.m16n8k8.row.col.f32.tf32.tf32.f32 "
        "{%0,%1,%2,%3},{%4,%5,%6,%7},{%8,%9},{%0,%1,%2,%3};"
        : "+f"(c[0]), "+f"(c[1]), "+f"(c[2]), "+f"(c[3])
        : "r"(a[0]), "r"(a[1]), "r"(a[2]), "r"(a[3]), "r"(b[0]), "r"(b[1]));
}
#define CP_ASYNC16(dst, src)                                        \
    asm volatile("cp.async.cg.shared.global [%0], [%1], 16;" ::    \
                     "r"(dst), "l"(src))
#define CP_COMMIT() asm volatile("cp.async.commit_group;")
#define CP_WAIT0() asm volatile("cp.async.wait_group 0;")

// ---------------------------------------------------------------------------
// Weight prepass: elementwise tf32 round ([k][n] layout kept)
// ---------------------------------------------------------------------------
__global__ __launch_bounds__(256) void cvt_w(const float* __restrict__ W,
                                             uint32_t* __restrict__ Wt) {
    const int i = blockIdx.x * 1024 + threadIdx.x * 4;
    float4 v = *(const float4*)&W[i];
    uint4 o;
    o.x = f2tf32(v.x); o.y = f2tf32(v.y);
    o.z = f2tf32(v.z); o.w = f2tf32(v.w);
    *(uint4*)&Wt[i] = o;
}

// ---------------------------------------------------------------------------
// tf32 register-MMA GEMM, block 128x256, warp tile 64x64, BK=32, 2 stages,
// single __syncthreads per main-loop iteration.
// A: LDG->cvt.rna->STS.  B: cp.async (pre-rounded tf32).
// ---------------------------------------------------------------------------
#define AST 36     // A row stride words (32 + 4 pad)
#define BST 264    // B row stride words (256 + 8 pad)
#define ASW (128 * AST)                 // 4608 words
#define STGW (ASW + 32 * BST)           // 13056 words/stage
#define GEMM_SMEM (2 * STGW * 4)        // 104448 B

template <bool SPLIT>
__global__ __launch_bounds__(256, 1) void gemm_reg(
    const float* __restrict__ A, const uint32_t* __restrict__ Wt,
    const float* __restrict__ bias, float* __restrict__ C) {
    extern __shared__ uint32_t sh[];
    const uint32_t sbase = smem_u32(sh);
    const int tid = threadIdx.x;
    const int lane = tid & 31;
    const int warp = tid >> 5;
    const int wm = (warp >> 2) * 64;   // 2 warp-rows
    const int wn = (warp & 3) * 64;    // 4 warp-cols
    const int row0 = blockIdx.y * 128;
    const int col0 = blockIdx.x * 256;
    const int lr = lane >> 2;
    const int lc = lane & 3;

    float acc[4][8][4];
#pragma unroll
    for (int i = 0; i < 4; i++)
#pragma unroll
        for (int j = 0; j < 8; j++)
#pragma unroll
            for (int e = 0; e < 4; e++) acc[i][j][e] = 0.0f;

    float4 ar[4];

    auto ldgA = [&](int kt) {
#pragma unroll
        for (int it = 0; it < 4; it++) {
            const int cid = it * 256 + tid;
            ar[it] = *(const float4*)&A[(size_t)(row0 + (cid >> 3)) * D_ +
                                        kt * 32 + (cid & 7) * 4];
        }
    };
    auto stsA = [&](int s) {
#pragma unroll
        for (int it = 0; it < 4; it++) {
            const int cid = it * 256 + tid;
            uint32_t* p = &sh[s * STGW + (cid >> 3) * AST + (cid & 7) * 4];
            p[0] = f2tf32(ar[it].x); p[1] = f2tf32(ar[it].y);
            p[2] = f2tf32(ar[it].z); p[3] = f2tf32(ar[it].w);
        }
    };
    auto cpB = [&](int kt, int s) {
#pragma unroll
        for (int it = 0; it < 8; it++) {
            const int cid = it * 256 + tid;
            const int row = cid >> 6;
            const int c4 = (cid & 63) * 4;
            const uint32_t dst =
                sbase + (s * STGW + ASW + row * BST + c4) * 4;
            CP_ASYNC16(dst, &Wt[(size_t)(kt * 32 + row) * N_ + col0 + c4]);
        }
        CP_COMMIT();
    };

    // prologue
    ldgA(0);
    cpB(0, 0);
    stsA(0);
    CP_WAIT0();
    __syncthreads();

    for (int kt = 0; kt < 32; kt++) {
        const int s = kt & 1;
        if (kt < 31) {
            ldgA(kt + 1);
            cpB(kt + 1, s ^ 1);
        }

        const uint32_t* Ab = &sh[s * STGW];
        const uint32_t* Bb = &sh[s * STGW + ASW];
#pragma unroll
        for (int ks = 0; ks < 4; ks++) {
            const int k = ks * 8;
            uint32_t af[4][4];
#pragma unroll
            for (int mt = 0; mt < 4; mt++) {
                const int r = wm + mt * 16 + lr;
                af[mt][0] = Ab[r * AST + k + lc];
                af[mt][1] = Ab[(r + 8) * AST + k + lc];
                af[mt][2] = Ab[r * AST + k + 4 + lc];
                af[mt][3] = Ab[(r + 8) * AST + k + 4 + lc];
            }
#pragma unroll
            for (int nt = 0; nt < 8; nt++) {
                uint32_t bf[2];
                const int c = wn + nt * 8 + lr;
                bf[0] = Bb[(k + lc) * BST + c];
                bf[1] = Bb[(k + 4 + lc) * BST + c];
#pragma unroll
                for (int mt = 0; mt < 4; mt++) mma_tf32(acc[mt][nt], af[mt], bf);
            }
        }

        if (kt < 31) {
            stsA(s ^ 1);
            CP_WAIT0();
        }
        __syncthreads();
    }

    // epilogue
#pragma unroll
    for (int mt = 0; mt < 4; mt++) {
#pragma unroll
        for (int nt = 0; nt < 8; nt++) {
            const int c = col0 + wn + nt * 8 + 2 * lc;
            const float bz0 = bias[c], bz1 = bias[c + 1];
#pragma unroll
            for (int half = 0; half < 2; half++) {
                const int m = row0 + wm + mt * 16 + lr + half * 8;
                float v0 = acc[mt][nt][half * 2 + 0] + bz0;
                float v1 = acc[mt][nt][half * 2 + 1] + bz1;
                if (SPLIT) {
                    v0 = __uint_as_float(f2tf32(v0));
                    v1 = __uint_as_float(f2tf32(v1));
                    const int b = m >> 11, l = m & (L_ - 1);
                    const int h = c >> 6, dk = c & (DK_ - 1);
                    float* p = &C[((((size_t)b * H_ + h) * L_) + l) * DK_ + dk];
                    p[0] = v0; p[1] = v1;
                } else {
                    C[(size_t)m * N_ + c] = v0;
                    C[(size_t)m * N_ + c + 1] = v1;
                }
            }
        }
    }
}

// ---------------------------------------------------------------------------
// Flash attention, tf32 register MMA, cp.async double-buffered K/V,
// Q fragments in registers (scaled by 0.125*log2e; softmax in ex2 domain),
// single __syncthreads per key tile.
// smem words: K[2][64*68] | V[2][64*72] | P[128*68]   (= 106496 B)
// ---------------------------------------------------------------------------
#define KSTR 68
#define VSTR 72
#define PSTR 68
#define KOFF(s) ((s) * (64 * KSTR))
#define VOFF(s) (2 * 64 * KSTR + (s) * (64 * VSTR))
#define POFF (2 * 64 * KSTR + 2 * 64 * VSTR)
#define ATTN_SMEM ((POFF + 128 * PSTR) * 4)    // 106496

#define QSCALE 0.18033688011112042f  // 0.125 * log2(e)

__global__ __launch_bounds__(256, 2) void attn2(
    const float* __restrict__ q, const float* __restrict__ k,
    const float* __restrict__ v, float* __restrict__ ctx) {
    extern __shared__ uint32_t sh[];
    const uint32_t sbase = smem_u32(sh);
    const int tid = threadIdx.x;
    const int lane = tid & 31;
    const int warp = tid >> 5;
    const int lr = lane >> 2;
    const int lc = lane & 3;
    const int m0 = warp * 16;
    const int bh = blockIdx.y;
    const int q0 = blockIdx.x * 128;

    const float* qbase = q + (size_t)bh * L_ * DK_ + (size_t)q0 * DK_;
    const float* kbase = k + (size_t)bh * L_ * DK_;
    const float* vbase = v + (size_t)bh * L_ * DK_;

    auto cpKV = [&](int jn, int s) {
#pragma unroll
        for (int it = 0; it < 4; it++) {
            const int cid = it * 256 + tid;
            const int row = cid >> 4;
            const int c4 = (cid & 15) * 4;
            const uint32_t dk = sbase + (KOFF(s) + row * KSTR + c4) * 4;
            CP_ASYNC16(dk, &kbase[(size_t)(jn * 64 + row) * DK_ + c4]);
            const uint32_t dv = sbase + (VOFF(s) + row * VSTR + c4) * 4;
            CP_ASYNC16(dv, &vbase[(size_t)(jn * 64 + row) * DK_ + c4]);
        }
        CP_COMMIT();
    };

    // stage Q into P region + first KV tile
#pragma unroll
    for (int it = 0; it < 8; it++) {
        const int cid = it * 256 + tid;
        const int row = cid >> 4;
        const int c4 = (cid & 15) * 4;
        const uint32_t dst = sbase + (POFF + row * PSTR + c4) * 4;
        CP_ASYNC16(dst, &qbase[(size_t)row * DK_ + c4]);
    }
    CP_COMMIT();
    cpKV(0, 0);
    CP_WAIT0();
    __syncthreads();

    // Q fragments -> registers, scaled into ex2 domain
    uint32_t qf[8][4];
#pragma unroll
    for (int kt = 0; kt < 8; kt++) {
        const int kk = kt * 8;
        const uint32_t* P = &sh[POFF];
        uint32_t t0 = P[(m0 + lr) * PSTR + kk + lc];
        uint32_t t1 = P[(m0 + lr + 8) * PSTR + kk + lc];
        uint32_t t2 = P[(m0 + lr) * PSTR + kk + 4 + lc];
        uint32_t t3 = P[(m0 + lr + 8) * PSTR + kk + 4 + lc];
        qf[kt][0] = __float_as_uint(__uint_as_float(t0) * QSCALE);
        qf[kt][1] = __float_as_uint(__uint_as_float(t1) * QSCALE);
        qf[kt][2] = __float_as_uint(__uint_as_float(t2) * QSCALE);
        qf[kt][3] = __float_as_uint(__uint_as_float(t3) * QSCALE);
    }

    float oacc[8][4];
#pragma unroll
    for (int vt = 0; vt < 8; vt++)
#pragma unroll
        for (int e = 0; e < 4; e++) oacc[vt][e] = 0.0f;
    float mrow0 = -1e30f, mrow1 = -1e30f, lrow0 = 0.0f, lrow1 = 0.0f;

    for (int jt = 0; jt < 32; jt++) {
        const int s = jt & 1;
        if (jt > 0) {
            CP_WAIT0();        // KV(jt) arrived
            __syncthreads();   // all warps done with stage s from jt-2
        }
        if (jt < 31) cpKV(jt + 1, s ^ 1);

        const uint32_t* Kb = &sh[KOFF(s)];
        const uint32_t* Vb = &sh[VOFF(s)];
        uint32_t* Pb = &sh[POFF];

        // S = Q K^T  (log2-domain logits)
        float sacc[8][4];
#pragma unroll
        for (int nt = 0; nt < 8; nt++)
#pragma unroll
            for (int e = 0; e < 4; e++) sacc[nt][e] = 0.0f;
#pragma unroll
        for (int kt = 0; kt < 8; kt++) {
            const int kk = kt * 8;
#pragma unroll
            for (int nt = 0; nt < 8; nt++) {
                uint32_t bf[2];
                bf[0] = Kb[(nt * 8 + lr) * KSTR + kk + lc];
                bf[1] = Kb[(nt * 8 + lr) * KSTR + kk + 4 + lc];
                mma_tf32(sacc[nt], qf[kt], bf);
            }
        }

        // online softmax (ex2 domain)
        float mx0 = -1e30f, mx1 = -1e30f;
#pragma unroll
        for (int nt = 0; nt < 8; nt++) {
            mx0 = fmaxf(mx0, fmaxf(sacc[nt][0], sacc[nt][1]));
            mx1 = fmaxf(mx1, fmaxf(sacc[nt][2], sacc[nt][3]));
        }
        mx0 = fmaxf(mx0, __shfl_xor_sync(0xffffffffu, mx0, 1));
        mx0 = fmaxf(mx0, __shfl_xor_sync(0xffffffffu, mx0, 2));
        mx1 = fmaxf(mx1, __shfl_xor_sync(0xffffffffu, mx1, 1));
        mx1 = fmaxf(mx1, __shfl_xor_sync(0xffffffffu, mx1, 2));
        const float mn0 = fmaxf(mrow0, mx0);
        const float mn1 = fmaxf(mrow1, mx1);
        const float al0 = ex2(mrow0 - mn0);
        const float al1 = ex2(mrow1 - mn1);
        mrow0 = mn0; mrow1 = mn1;

        float sum0 = 0.0f, sum1 = 0.0f;
#pragma unroll
        for (int nt = 0; nt < 8; nt++) {
            const float p0 = ex2(sacc[nt][0] - mn0);
            const float p1 = ex2(sacc[nt][1] - mn0);
            const float p2 = ex2(sacc[nt][2] - mn1);
            const float p3 = ex2(sacc[nt][3] - mn1);
            sum0 += p0 + p1; sum1 += p2 + p3;
            const int c = nt * 8 + 2 * lc;
            uint32_t* pl = &Pb[(m0 + lr) * PSTR + c];
            pl[0] = f2tf32(p0); pl[1] = f2tf32(p1);
            uint32_t* ph = &Pb[(m0 + lr + 8) * PSTR + c];
            ph[0] = f2tf32(p2); ph[1] = f2tf32(p3);
        }
        sum0 += __shfl_xor_sync(0xffffffffu, sum0, 1);
        sum0 += __shfl_xor_sync(0xffffffffu, sum0, 2);
        sum1 += __shfl_xor_sync(0xffffffffu, sum1, 1);
        sum1 += __shfl_xor_sync(0xffffffffu, sum1, 2);
        lrow0 = lrow0 * al0 + sum0;
        lrow1 = lrow1 * al1 + sum1;
#pragma unroll
        for (int vt = 0; vt < 8; vt++) {
            oacc[vt][0] *= al0; oacc[vt][1] *= al0;
            oacc[vt][2] *= al1; oacc[vt][3] *= al1;
        }
        __syncwarp();  // warp reads only its own P rows

        // O += P V
#pragma unroll
        for (int pt = 0; pt < 8; pt++) {
            const int pp = pt * 8;
            uint32_t af[4];
            af[0] = Pb[(m0 + lr) * PSTR + pp + lc];
            af[1] = Pb[(m0 + lr + 8) * PSTR + pp + lc];
            af[2] = Pb[(m0 + lr) * PSTR + pp + 4 + lc];
            af[3] = Pb[(m0 + lr + 8) * PSTR + pp + 4 + lc];
#pragma unroll
            for (int vt = 0; vt < 8; vt++) {
                uint32_t bf[2];
                bf[0] = Vb[(pp + lc) * VSTR + vt * 8 + lr];
                bf[1] = Vb[(pp + 4 + lc) * VSTR + vt * 8 + lr];
                mma_tf32(oacc[vt], af, bf);
            }
        }
        // no bottom barrier: next iteration's top barrier protects stage reuse
    }

    // epilogue: normalize, write ctx [B, L, H*DV]
    const int b = bh >> 4;
    const int h = bh & (H_ - 1);
    const float inv0 = 1.0f / lrow0;
    const float inv1 = 1.0f / lrow1;
    const int r0 = q0 + m0 + lr;
#pragma unroll
    for (int vt = 0; vt < 8; vt++) {
        const int c = h * DK_ + vt * 8 + 2 * lc;
        float* p0 = &ctx[((size_t)b * L_ + r0) * N_ + c];
        p0[0] = oacc[vt][0] * inv0; p0[1] = oacc[vt][1] * inv0;
        float* p1 = &ctx[((size_t)b * L_ + r0 + 8) * N_ + c];
        p1[0] = oacc[vt][2] * inv1; p1[1] = oacc[vt][3] * inv1;
    }
}

// ---------------------------------------------------------------------------
extern "C" void kernel_launch(void* const* d_in, const int* in_sizes, int n_in,
                              void* d_out, int out_size) {
    const float* query = (const float*)d_in[0];
    const float* key   = (const float*)d_in[1];
    const float* value = (const float*)d_in[2];
    const float* W_q   = (const float*)d_in[3];
    const float* b_q   = (const float*)d_in[4];
    const float* W_k   = (const float*)d_in[5];
    const float* b_k   = (const float*)d_in[6];
    const float* W_v   = (const float*)d_in[7];
    const float* b_v   = (const float*)d_in[8];
    const float* W_o   = (const float*)d_in[9];
    const float* b_o   = (const float*)d_in[10];
    float* out = (float*)d_out;

    float *qp, *kp, *vp, *cp;
    uint32_t* wt;
    cudaGetSymbolAddress((void**)&qp, g_q);
    cudaGetSymbolAddress((void**)&kp, g_k);
    cudaGetSymbolAddress((void**)&vp, g_v);
    cudaGetSymbolAddress((void**)&cp, g_ctx);
    cudaGetSymbolAddress((void**)&wt, g_wt);

    cudaFuncSetAttribute(gemm_reg<true>,
                         cudaFuncAttributeMaxDynamicSharedMemorySize, GEMM_SMEM);
    cudaFuncSetAttribute(gemm_reg<false>,
                         cudaFuncAttributeMaxDynamicSharedMemorySize, GEMM_SMEM);
    cudaFuncSetAttribute(attn2, cudaFuncAttributeMaxDynamicSharedMemorySize,
                         ATTN_SMEM);

    cvt_w<<<1024, 256>>>(W_q, wt + 0ull * D_ * N_);
    cvt_w<<<1024, 256>>>(W_k, wt + 1ull * D_ * N_);
    cvt_w<<<1024, 256>>>(W_v, wt + 2ull * D_ * N_);
    cvt_w<<<1024, 256>>>(W_o, wt + 3ull * D_ * N_);

    dim3 ggrid(N_ / 256, M_ / 128);  // (4, 64)
    gemm_reg<true><<<ggrid, 256, GEMM_SMEM>>>(query, wt + 0ull * D_ * N_, b_q, qp);
    gemm_reg<true><<<ggrid, 256, GEMM_SMEM>>>(key, wt + 1ull * D_ * N_, b_k, kp);
    gemm_reg<true><<<ggrid, 256, GEMM_SMEM>>>(value, wt + 2ull * D_ * N_, b_v, vp);

    dim3 agrid(L_ / 128, B_ * H_);   // (16, 64)
    attn2<<<agrid, 256, ATTN_SMEM>>>(qp, kp, vp, cp);

    gemm_reg<false><<<ggrid, 256, GEMM_SMEM>>>(cp, wt + 3ull * D_ * N_, b_o, out);
}